// round 1
// baseline (speedup 1.0000x reference)
#include <cuda_runtime.h>
#include <cuda_bf16.h>
#include <math.h>

// ---------------- constants ----------------
#define Hdim 768
#define NH 12
#define NKV 4
#define HD 64
#define IM 3072
#define KCONV 4
#define SEQ 1024
#define BATCH 2
#define ROWS (BATCH*SEQ)      // 2048
#define VOCAB 50304
#define H3 (3*Hdim)           // 2304

// ---------------- scratch (device globals; no allocation) ----------------
__device__ float g_x [ROWS*Hdim];
__device__ float g_h [ROWS*Hdim];
__device__ float g_q [ROWS*Hdim];
__device__ float g_k [ROWS*NKV*HD];
__device__ float g_v [ROWS*NKV*HD];
__device__ float g_ao[ROWS*Hdim];
__device__ float g_t1[ROWS*IM];
__device__ float g_t2[ROWS*IM];

// ---------------- embedding gather ----------------
__global__ void embed_kernel(const int* __restrict__ tok, const float* __restrict__ E,
                             float* __restrict__ X) {
    int row = blockIdx.x;
    int t = tok[row];
    const float* src = E + (size_t)t * Hdim;
    float* dst = X + (size_t)row * Hdim;
    for (int c = threadIdx.x; c < Hdim; c += blockDim.x) dst[c] = src[c];
}

// ---------------- rmsnorm over n cols (block per row) ----------------
__global__ void rmsnorm_kernel(const float* __restrict__ X, const float* __restrict__ W,
                               float* __restrict__ Y, int n) {
    int row = blockIdx.x;
    const float* x = X + (size_t)row * n;
    float* y = Y + (size_t)row * n;
    float s = 0.f;
    for (int c = threadIdx.x; c < n; c += blockDim.x) { float v = x[c]; s += v * v; }
    __shared__ float sm[32];
    #pragma unroll
    for (int o = 16; o; o >>= 1) s += __shfl_xor_sync(~0u, s, o);
    if ((threadIdx.x & 31) == 0) sm[threadIdx.x >> 5] = s;
    __syncthreads();
    if (threadIdx.x < 32) {
        float v = (threadIdx.x < (blockDim.x >> 5)) ? sm[threadIdx.x] : 0.f;
        #pragma unroll
        for (int o = 4; o; o >>= 1) v += __shfl_xor_sync(~0u, v, o);
        if (threadIdx.x == 0) sm[0] = v;
    }
    __syncthreads();
    float r = rsqrtf(sm[0] / (float)n + 1e-6f);
    for (int c = threadIdx.x; c < n; c += blockDim.x) y[c] = x[c] * r * W[c];
}

// ---------------- generic SGEMM: C[M,N] = A[M,K] * B[N,K]^T (+bias[n]) (+res) ----------------
__global__ void __launch_bounds__(256) sgemm_nt(
    const float* __restrict__ A, const float* __restrict__ B, float* __restrict__ C,
    int M, int N, int K, const float* __restrict__ bias, const float* __restrict__ res) {
    __shared__ float As[16][128];
    __shared__ float Bs[16][128];
    const int tid = threadIdx.x;
    const int bm = blockIdx.y * 128, bn = blockIdx.x * 128;
    const int lrow = tid >> 2;          // 0..63
    const int lcol = (tid & 3) * 4;     // 0,4,8,12
    const int tx = tid & 15, ty = tid >> 4;
    float acc[8][8];
    #pragma unroll
    for (int i = 0; i < 8; i++)
        #pragma unroll
        for (int j = 0; j < 8; j++) acc[i][j] = 0.f;
    const float* Ab = A + (size_t)bm * K;
    const float* Bb = B + (size_t)bn * K;
    for (int k0 = 0; k0 < K; k0 += 16) {
        #pragma unroll
        for (int r = 0; r < 2; r++) {
            int row = lrow + r * 64;
            float4 va = *(const float4*)(Ab + (size_t)row * K + k0 + lcol);
            As[lcol + 0][row] = va.x; As[lcol + 1][row] = va.y;
            As[lcol + 2][row] = va.z; As[lcol + 3][row] = va.w;
            float4 vb = *(const float4*)(Bb + (size_t)row * K + k0 + lcol);
            Bs[lcol + 0][row] = vb.x; Bs[lcol + 1][row] = vb.y;
            Bs[lcol + 2][row] = vb.z; Bs[lcol + 3][row] = vb.w;
        }
        __syncthreads();
        #pragma unroll
        for (int k = 0; k < 16; k++) {
            float a[8], b[8];
            *(float4*)(a)     = *(const float4*)&As[k][ty * 8];
            *(float4*)(a + 4) = *(const float4*)&As[k][ty * 8 + 4];
            *(float4*)(b)     = *(const float4*)&Bs[k][tx * 8];
            *(float4*)(b + 4) = *(const float4*)&Bs[k][tx * 8 + 4];
            #pragma unroll
            for (int i = 0; i < 8; i++)
                #pragma unroll
                for (int j = 0; j < 8; j++) acc[i][j] += a[i] * b[j];
        }
        __syncthreads();
    }
    #pragma unroll
    for (int i = 0; i < 8; i++) {
        int m = bm + ty * 8 + i;
        float* cp = C + (size_t)m * N + bn + tx * 8;
        const float* rp = res ? (res + (size_t)m * N + bn + tx * 8) : nullptr;
        #pragma unroll
        for (int j = 0; j < 8; j++) {
            float v = acc[i][j];
            if (bias) v += bias[bn + tx * 8 + j];
            if (rp)   v += rp[j];
            cp[j] = v;
        }
    }
}

// ---------------- per-head RMSNorm (q/k) + RoPE ----------------
// one warp per (row, head); heads 0..11 = q heads, 12..15 = kv heads
__global__ void qknorm_rope_kernel(float* __restrict__ Q, float* __restrict__ Kt,
                                   const float* __restrict__ qln, const float* __restrict__ kln) {
    int w = threadIdx.x >> 5, l = threadIdx.x & 31;
    int g = blockIdx.x * 8 + w;           // 0 .. ROWS*16
    int hh = g & 15;
    int row = g >> 4;
    int s = row & (SEQ - 1);
    float* p; const float* wn;
    if (hh < NH) { p = Q  + ((size_t)row * NH  + hh)        * HD; wn = qln; }
    else         { p = Kt + ((size_t)row * NKV + (hh - NH)) * HD; wn = kln; }
    float a = p[l], b = p[l + 32];
    float ss = a * a + b * b;
    #pragma unroll
    for (int o = 16; o; o >>= 1) ss += __shfl_xor_sync(~0u, ss, o);
    float r = rsqrtf(ss * (1.0f / HD) + 1e-6f);
    a *= r * wn[l];
    b *= r * wn[l + 32];
    float inv = powf(10000.0f, -((float)l) / 32.0f);
    float ang = (float)s * inv;
    float cs = cosf(ang), sn = sinf(ang);
    p[l]      = a * cs - b * sn;
    p[l + 32] = b * cs + a * sn;
}

// ---------------- causal attention, exact softmax, one warp per query row ----------------
__global__ void attn_kernel(const float* __restrict__ Q, const float* __restrict__ K,
                            const float* __restrict__ V, float* __restrict__ O) {
    __shared__ float qs[8][HD];
    __shared__ float sc[8][SEQ];
    int w = threadIdx.x >> 5, l = threadIdx.x & 31;
    int g = blockIdx.x * 8 + w;           // ((b*NH + h)*SEQ + s)
    int s = g & (SEQ - 1);
    int bh = g >> 10;
    int h = bh % NH, b = bh / NH;
    int kvh = h / (NH / NKV);
    const float* qp = Q + (((size_t)(b * SEQ + s)) * NH + h) * HD;
    qs[w][l] = qp[l]; qs[w][l + 32] = qp[l + 32];
    __syncwarp();
    const float* Kb = K + ((size_t)b * SEQ * NKV + kvh) * HD;
    const float* Vb = V + ((size_t)b * SEQ * NKV + kvh) * HD;
    for (int j = l; j <= s; j += 32) {
        const float4* kp = (const float4*)(Kb + (size_t)j * (NKV * HD));
        float d = 0.f;
        #pragma unroll
        for (int i = 0; i < 16; i++) {
            float4 kk = kp[i];
            d += qs[w][4*i] * kk.x + qs[w][4*i+1] * kk.y + qs[w][4*i+2] * kk.z + qs[w][4*i+3] * kk.w;
        }
        sc[w][j] = d * 0.125f;
    }
    __syncwarp();
    float m = -1e30f;
    for (int j = l; j <= s; j += 32) m = fmaxf(m, sc[w][j]);
    #pragma unroll
    for (int o = 16; o; o >>= 1) m = fmaxf(m, __shfl_xor_sync(~0u, m, o));
    float sum = 0.f;
    for (int j = l; j <= s; j += 32) { float p = expf(sc[w][j] - m); sc[w][j] = p; sum += p; }
    #pragma unroll
    for (int o = 16; o; o >>= 1) sum += __shfl_xor_sync(~0u, sum, o);
    __syncwarp();
    float oa = 0.f, ob = 0.f;
    int j = 0;
    for (; j + 4 <= s + 1; j += 4) {
        #pragma unroll
        for (int u = 0; u < 4; u++) {
            float p = sc[w][j + u];
            const float* vp = Vb + (size_t)(j + u) * (NKV * HD);
            oa += p * vp[l]; ob += p * vp[l + 32];
        }
    }
    for (; j <= s; j++) {
        float p = sc[w][j];
        const float* vp = Vb + (size_t)j * (NKV * HD);
        oa += p * vp[l]; ob += p * vp[l + 32];
    }
    float invs = 1.0f / sum;
    float* op = O + (((size_t)(b * SEQ + s)) * NH + h) * HD;
    op[l] = oa * invs; op[l + 32] = ob * invs;
}

// ---------------- causal depthwise conv: y = Cg * (conv(Bg*xg) + cb) ----------------
__global__ void conv_kernel(const float* __restrict__ T, const float* __restrict__ W4,
                            const float* __restrict__ cb, float* __restrict__ Y) {
    int idx = blockIdx.x * blockDim.x + threadIdx.x;  // ROWS*Hdim
    int c = idx % Hdim;
    int row = idx / Hdim;
    int s = row & (SEQ - 1);
    int b = row / SEQ;
    const float* w = W4 + (size_t)c * KCONV;
    float acc = cb[c];
    #pragma unroll
    for (int j = 0; j < KCONV; j++) {
        int sp = s - (KCONV - 1) + j;
        if (sp >= 0) {
            const float* tr = T + ((size_t)(b * SEQ + sp)) * H3;
            acc += w[j] * tr[c] * tr[2 * Hdim + c];
        }
    }
    float Cg = T[(size_t)row * H3 + Hdim + c];
    Y[(size_t)row * Hdim + c] = Cg * acc;
}

// ---------------- silu(gate)*up, in-place into t1 ----------------
__global__ void silu_mul_kernel(float* __restrict__ G, const float* __restrict__ U, int n) {
    int i = blockIdx.x * blockDim.x + threadIdx.x;
    if (i < n) {
        float g = G[i];
        G[i] = (g / (1.0f + expf(-g))) * U[i];
    }
}

// ---------------- host-side plumbing ----------------
static void gemm(const float* A, const float* B, float* C, int M, int N, int K,
                 const float* bias, const float* res) {
    dim3 grid(N / 128, M / 128);
    sgemm_nt<<<grid, 256>>>(A, B, C, M, N, K, bias, res);
}

extern "C" void kernel_launch(void* const* d_in, const int* in_sizes, int n_in,
                              void* d_out, int out_size) {
    const int*   tokens  = (const int*)  d_in[0];
    const float* embed   = (const float*)d_in[1];
    const float* qw      = (const float*)d_in[2];
    const float* kw      = (const float*)d_in[3];
    const float* vw      = (const float*)d_in[4];
    const float* ow      = (const float*)d_in[5];
    const float* qln     = (const float*)d_in[6];
    const float* kln     = (const float*)d_in[7];
    const float* a_gate  = (const float*)d_in[8];
    const float* a_up    = (const float*)d_in[9];
    const float* a_down  = (const float*)d_in[10];
    const float* a_ln1   = (const float*)d_in[11];
    const float* a_ln2   = (const float*)d_in[12];
    const float* conv_w  = (const float*)d_in[13];
    const float* conv_b  = (const float*)d_in[14];
    const float* in_w    = (const float*)d_in[15];
    const float* in_b    = (const float*)d_in[16];
    const float* out_w   = (const float*)d_in[17];
    const float* out_b   = (const float*)d_in[18];
    const float* c_gate  = (const float*)d_in[19];
    const float* c_up    = (const float*)d_in[20];
    const float* c_down  = (const float*)d_in[21];
    const float* c_ln1   = (const float*)d_in[22];
    const float* c_ln2   = (const float*)d_in[23];
    const float* finln   = (const float*)d_in[24];
    const float* lm_head = (const float*)d_in[25];

    float *x, *h, *q, *k, *v, *ao, *t1, *t2;
    cudaGetSymbolAddress((void**)&x,  g_x);
    cudaGetSymbolAddress((void**)&h,  g_h);
    cudaGetSymbolAddress((void**)&q,  g_q);
    cudaGetSymbolAddress((void**)&k,  g_k);
    cudaGetSymbolAddress((void**)&v,  g_v);
    cudaGetSymbolAddress((void**)&ao, g_ao);
    cudaGetSymbolAddress((void**)&t1, g_t1);
    cudaGetSymbolAddress((void**)&t2, g_t2);

    embed_kernel<<<ROWS, 256>>>(tokens, embed, x);

    int ai = 0, ci = 0;
    for (int l = 0; l < 12; l++) {
        bool full = (l == 2 || l == 5 || l == 8 || l == 11);
        if (full) {
            rmsnorm_kernel<<<ROWS, 256>>>(x, a_ln1 + (size_t)ai * Hdim, h, Hdim);
            gemm(h, qw + (size_t)ai * Hdim * Hdim,      q, ROWS, Hdim,     Hdim, 0, 0);
            gemm(h, kw + (size_t)ai * NKV * HD * Hdim,  k, ROWS, NKV * HD, Hdim, 0, 0);
            gemm(h, vw + (size_t)ai * NKV * HD * Hdim,  v, ROWS, NKV * HD, Hdim, 0, 0);
            qknorm_rope_kernel<<<ROWS * 16 / 8, 256>>>(q, k, qln + (size_t)ai * HD, kln + (size_t)ai * HD);
            attn_kernel<<<BATCH * NH * SEQ / 8, 256>>>(q, k, v, ao);
            gemm(ao, ow + (size_t)ai * Hdim * Hdim, x, ROWS, Hdim, Hdim, 0, x);
            rmsnorm_kernel<<<ROWS, 256>>>(x, a_ln2 + (size_t)ai * Hdim, h, Hdim);
            gemm(h, a_gate + (size_t)ai * IM * Hdim, t1, ROWS, IM, Hdim, 0, 0);
            gemm(h, a_up   + (size_t)ai * IM * Hdim, t2, ROWS, IM, Hdim, 0, 0);
            silu_mul_kernel<<<(ROWS * IM) / 256, 256>>>(t1, t2, ROWS * IM);
            gemm(t1, a_down + (size_t)ai * Hdim * IM, x, ROWS, Hdim, IM, 0, x);
            ai++;
        } else {
            rmsnorm_kernel<<<ROWS, 256>>>(x, c_ln1 + (size_t)ci * Hdim, h, Hdim);
            gemm(h, in_w + (size_t)ci * H3 * Hdim, t1, ROWS, H3, Hdim, in_b + (size_t)ci * H3, 0);
            conv_kernel<<<(ROWS * Hdim) / 256, 256>>>(t1, conv_w + (size_t)ci * Hdim * KCONV,
                                                      conv_b + (size_t)ci * Hdim, t2);
            gemm(t2, out_w + (size_t)ci * Hdim * Hdim, x, ROWS, Hdim, Hdim,
                 out_b + (size_t)ci * Hdim, x);
            rmsnorm_kernel<<<ROWS, 256>>>(x, c_ln2 + (size_t)ci * Hdim, h, Hdim);
            gemm(h, c_gate + (size_t)ci * IM * Hdim, t1, ROWS, IM, Hdim, 0, 0);
            gemm(h, c_up   + (size_t)ci * IM * Hdim, t2, ROWS, IM, Hdim, 0, 0);
            silu_mul_kernel<<<(ROWS * IM) / 256, 256>>>(t1, t2, ROWS * IM);
            gemm(t1, c_down + (size_t)ci * Hdim * IM, x, ROWS, Hdim, IM, 0, x);
            ci++;
        }
    }
    rmsnorm_kernel<<<ROWS, 256>>>(x, finln, h, Hdim);
    gemm(h, lm_head, (float*)d_out, ROWS, VOCAB, Hdim, 0, 0);
}

// round 2
// speedup vs baseline: 2.2359x; 2.2359x over previous
#include <cuda_runtime.h>
#include <cuda_bf16.h>
#include <math.h>

// ---------------- constants ----------------
#define Hdim 768
#define NH 12
#define NKV 4
#define HD 64
#define IM 3072
#define KCONV 4
#define SEQ 1024
#define BATCH 2
#define ROWS (BATCH*SEQ)      // 2048
#define VOCAB 50304
#define H3 (3*Hdim)           // 2304

// gemm tiling
#define BM 128
#define BN 128
#define BK 32
#define SSTR 40                       // padded row stride (bf16 elems) -> conflict-free ldmatrix
#define ARR_BYTES (128*SSTR*2)        // 10240
#define STAGE_BYTES (4*ARR_BYTES)     // 40960
#define SMEM_TOTAL (2*STAGE_BYTES)    // 81920

// ---------------- weight split offsets (elems) ----------------
#define OFF_QW   0ull
#define OFF_KW   2359296ull
#define OFF_VW   3145728ull
#define OFF_OW   3932160ull
#define OFF_AG   6291456ull
#define OFF_AU   15728640ull
#define OFF_AD   25165824ull
#define OFF_INW  34603008ull
#define OFF_OUTW 48758784ull
#define OFF_CG   53477376ull
#define OFF_CU   72351744ull
#define OFF_CD   91226112ull
#define OFF_LM   110100480ull
#define W_TOTAL  148733952ull

// ---------------- scratch (device globals; no allocation) ----------------
__device__ float g_x [ROWS*Hdim];
__device__ float g_q [ROWS*Hdim];
__device__ float g_k [ROWS*NKV*HD];
__device__ float g_v [ROWS*NKV*HD];
__device__ float g_t1[ROWS*IM];
__device__ float g_t2[ROWS*IM];
__device__ __nv_bfloat16 g_ah[ROWS*IM];
__device__ __nv_bfloat16 g_al[ROWS*IM];
__device__ __nv_bfloat16 g_wh[W_TOTAL];
__device__ __nv_bfloat16 g_wl[W_TOTAL];

// ---------------- helpers ----------------
__device__ __forceinline__ void split1(float x, __nv_bfloat16* h, __nv_bfloat16* l) {
    __nv_bfloat16 hh = __float2bfloat16(x);
    *h = hh;
    *l = __float2bfloat16(x - __bfloat162float(hh));
}

__device__ __forceinline__ unsigned cvta_s(const void* p) {
    return (unsigned)__cvta_generic_to_shared(p);
}
__device__ __forceinline__ void cp16(unsigned saddr, const void* g) {
    asm volatile("cp.async.cg.shared.global [%0], [%1], 16;\n" :: "r"(saddr), "l"(g));
}
__device__ __forceinline__ void ldm4(unsigned* r, unsigned addr) {
    asm volatile("ldmatrix.sync.aligned.m8n8.x4.shared.b16 {%0,%1,%2,%3}, [%4];\n"
                 : "=r"(r[0]), "=r"(r[1]), "=r"(r[2]), "=r"(r[3]) : "r"(addr));
}
__device__ __forceinline__ void mma16816(float* d, const unsigned* a, const unsigned* b) {
    asm volatile("mma.sync.aligned.m16n8k16.row.col.f32.bf16.bf16.f32 "
                 "{%0,%1,%2,%3}, {%4,%5,%6,%7}, {%8,%9}, {%0,%1,%2,%3};\n"
                 : "+f"(d[0]), "+f"(d[1]), "+f"(d[2]), "+f"(d[3])
                 : "r"(a[0]), "r"(a[1]), "r"(a[2]), "r"(a[3]), "r"(b[0]), "r"(b[1]));
}

// ---------------- weight split kernel (float4 vectorized) ----------------
__global__ void wsplit_kernel(const float4* __restrict__ X, __nv_bfloat16* __restrict__ H,
                              __nv_bfloat16* __restrict__ L) {
    int idx = blockIdx.x * blockDim.x + threadIdx.x;
    float4 v = X[idx];
    __nv_bfloat16 h[4], l[4];
    split1(v.x, &h[0], &l[0]); split1(v.y, &h[1], &l[1]);
    split1(v.z, &h[2], &l[2]); split1(v.w, &h[3], &l[3]);
    ((__nv_bfloat162*)H)[idx * 2]     = *(__nv_bfloat162*)&h[0];
    ((__nv_bfloat162*)H)[idx * 2 + 1] = *(__nv_bfloat162*)&h[2];
    ((__nv_bfloat162*)L)[idx * 2]     = *(__nv_bfloat162*)&l[0];
    ((__nv_bfloat162*)L)[idx * 2 + 1] = *(__nv_bfloat162*)&l[2];
}

// ---------------- embedding gather ----------------
__global__ void embed_kernel(const int* __restrict__ tok, const float* __restrict__ E,
                             float* __restrict__ X) {
    int row = blockIdx.x;
    int t = tok[row];
    const float* src = E + (size_t)t * Hdim;
    float* dst = X + (size_t)row * Hdim;
    for (int c = threadIdx.x; c < Hdim; c += blockDim.x) dst[c] = src[c];
}

// ---------------- rmsnorm -> bf16 hi/lo split output ----------------
__global__ void rmsnorm_split_kernel(const float* __restrict__ X, const float* __restrict__ W,
                                     __nv_bfloat16* __restrict__ Hh, __nv_bfloat16* __restrict__ Hl,
                                     int n) {
    int row = blockIdx.x;
    const float* x = X + (size_t)row * n;
    float s = 0.f;
    for (int c = threadIdx.x; c < n; c += blockDim.x) { float v = x[c]; s += v * v; }
    __shared__ float sm[32];
    #pragma unroll
    for (int o = 16; o; o >>= 1) s += __shfl_xor_sync(~0u, s, o);
    if ((threadIdx.x & 31) == 0) sm[threadIdx.x >> 5] = s;
    __syncthreads();
    if (threadIdx.x < 32) {
        float v = (threadIdx.x < (blockDim.x >> 5)) ? sm[threadIdx.x] : 0.f;
        #pragma unroll
        for (int o = 4; o; o >>= 1) v += __shfl_xor_sync(~0u, v, o);
        if (threadIdx.x == 0) sm[0] = v;
    }
    __syncthreads();
    float r = rsqrtf(sm[0] / (float)n + 1e-6f);
    for (int c = threadIdx.x; c < n; c += blockDim.x) {
        float y = x[c] * r * W[c];
        split1(y, &Hh[(size_t)row * n + c], &Hl[(size_t)row * n + c]);
    }
}

// ---------------- bf16x3 split GEMM: C[M,N] = A*B^T (+bias)(+res) ----------------
// A,B given as (hi,lo) bf16 pairs; computes Ah*Bh + Ah*Bl + Al*Bh in fp32 accum.
__global__ void __launch_bounds__(256) gemm_bf16x3(
    const __nv_bfloat16* __restrict__ Ah, const __nv_bfloat16* __restrict__ Al,
    const __nv_bfloat16* __restrict__ Bh, const __nv_bfloat16* __restrict__ Bl,
    float* __restrict__ C, int M, int N, int K,
    const float* __restrict__ bias, const float* __restrict__ res)
{
    extern __shared__ __align__(16) char sm_raw[];
    const int tid = threadIdx.x;
    const int lane = tid & 31, wid = tid >> 5;
    const int wm = wid >> 1, wn = wid & 1;
    const int bm = blockIdx.y * BM, bn = blockIdx.x * BN;
    const unsigned sbase = cvta_s(sm_raw);

    const int c4 = tid & 3;
    const int r0 = tid >> 2;     // 0..63

    const __nv_bfloat16* gA0 = Ah + (size_t)bm * K;
    const __nv_bfloat16* gA1 = Al + (size_t)bm * K;
    const __nv_bfloat16* gB0 = Bh + (size_t)bn * K;
    const __nv_bfloat16* gB1 = Bl + (size_t)bn * K;

    float acc[2][8][4];
    #pragma unroll
    for (int t = 0; t < 2; t++)
        #pragma unroll
        for (int n = 0; n < 8; n++)
            #pragma unroll
            for (int i = 0; i < 4; i++) acc[t][n][i] = 0.f;

    auto load_stage = [&](int st, int kt) {
        int gk = kt * BK + c4 * 8;
        unsigned s0 = sbase + st * STAGE_BYTES + (unsigned)(r0 * SSTR + c4 * 8) * 2;
        cp16(s0 + 0 * ARR_BYTES,                  gA0 + (size_t)r0 * K + gk);
        cp16(s0 + 0 * ARR_BYTES + 64 * SSTR * 2,  gA0 + (size_t)(r0 + 64) * K + gk);
        cp16(s0 + 1 * ARR_BYTES,                  gA1 + (size_t)r0 * K + gk);
        cp16(s0 + 1 * ARR_BYTES + 64 * SSTR * 2,  gA1 + (size_t)(r0 + 64) * K + gk);
        cp16(s0 + 2 * ARR_BYTES,                  gB0 + (size_t)r0 * K + gk);
        cp16(s0 + 2 * ARR_BYTES + 64 * SSTR * 2,  gB0 + (size_t)(r0 + 64) * K + gk);
        cp16(s0 + 3 * ARR_BYTES,                  gB1 + (size_t)r0 * K + gk);
        cp16(s0 + 3 * ARR_BYTES + 64 * SSTR * 2,  gB1 + (size_t)(r0 + 64) * K + gk);
    };

    const int KT = K / BK;
    load_stage(0, 0);
    asm volatile("cp.async.commit_group;\n");
    for (int kt = 0; kt < KT; kt++) {
        if (kt + 1 < KT) {
            load_stage((kt + 1) & 1, kt + 1);
            asm volatile("cp.async.commit_group;\n");
            asm volatile("cp.async.wait_group 1;\n");
        } else {
            asm volatile("cp.async.wait_group 0;\n");
        }
        __syncthreads();
        unsigned st = sbase + (kt & 1) * STAGE_BYTES;
        #pragma unroll
        for (int kk = 0; kk < BK; kk += 16) {
            unsigned ah[2][4], al[2][4], bh[8][2], bl[8][2];
            #pragma unroll
            for (int t = 0; t < 2; t++) {
                int row = wm * 32 + t * 16 + (lane & 15);
                int col = kk + ((lane >> 4) << 3);
                unsigned off = (unsigned)(row * SSTR + col) * 2;
                ldm4(ah[t], st + off);
                ldm4(al[t], st + ARR_BYTES + off);
            }
            #pragma unroll
            for (int p = 0; p < 4; p++) {
                int m = lane >> 3;
                int row = wn * 64 + p * 16 + ((m >> 1) << 3) + (lane & 7);
                int col = kk + ((m & 1) << 3);
                unsigned off = (unsigned)(row * SSTR + col) * 2;
                unsigned r[4];
                ldm4(r, st + 2 * ARR_BYTES + off);
                bh[2 * p][0] = r[0]; bh[2 * p][1] = r[1];
                bh[2 * p + 1][0] = r[2]; bh[2 * p + 1][1] = r[3];
                ldm4(r, st + 3 * ARR_BYTES + off);
                bl[2 * p][0] = r[0]; bl[2 * p][1] = r[1];
                bl[2 * p + 1][0] = r[2]; bl[2 * p + 1][1] = r[3];
            }
            #pragma unroll
            for (int t = 0; t < 2; t++)
                #pragma unroll
                for (int n = 0; n < 8; n++) {
                    mma16816(acc[t][n], ah[t], bh[n]);
                    mma16816(acc[t][n], ah[t], bl[n]);
                    mma16816(acc[t][n], al[t], bh[n]);
                }
        }
        __syncthreads();
    }

    // epilogue
    #pragma unroll
    for (int t = 0; t < 2; t++) {
        int row0 = bm + wm * 32 + t * 16 + (lane >> 2);
        #pragma unroll
        for (int n = 0; n < 8; n++) {
            int col = bn + wn * 64 + n * 8 + (lane & 3) * 2;
            #pragma unroll
            for (int hh = 0; hh < 2; hh++) {
                int row = row0 + hh * 8;
                float v0 = acc[t][n][hh * 2], v1 = acc[t][n][hh * 2 + 1];
                if (bias) { v0 += bias[col]; v1 += bias[col + 1]; }
                if (res) {
                    const float* rp = res + (size_t)row * N + col;
                    v0 += rp[0]; v1 += rp[1];
                }
                *(float2*)(C + (size_t)row * N + col) = make_float2(v0, v1);
            }
        }
    }
}

// ---------------- per-head RMSNorm (q/k) + RoPE ----------------
__global__ void qknorm_rope_kernel(float* __restrict__ Q, float* __restrict__ Kt,
                                   const float* __restrict__ qln, const float* __restrict__ kln) {
    int w = threadIdx.x >> 5, l = threadIdx.x & 31;
    int g = blockIdx.x * 8 + w;
    int hh = g & 15;
    int row = g >> 4;
    int s = row & (SEQ - 1);
    float* p; const float* wn;
    if (hh < NH) { p = Q  + ((size_t)row * NH  + hh)        * HD; wn = qln; }
    else         { p = Kt + ((size_t)row * NKV + (hh - NH)) * HD; wn = kln; }
    float a = p[l], b = p[l + 32];
    float ss = a * a + b * b;
    #pragma unroll
    for (int o = 16; o; o >>= 1) ss += __shfl_xor_sync(~0u, ss, o);
    float r = rsqrtf(ss * (1.0f / HD) + 1e-6f);
    a *= r * wn[l];
    b *= r * wn[l + 32];
    float inv = powf(10000.0f, -((float)l) / 32.0f);
    float ang = (float)s * inv;
    float cs = cosf(ang), sn = sinf(ang);
    p[l]      = a * cs - b * sn;
    p[l + 32] = b * cs + a * sn;
}

// ---------------- causal attention, exact softmax, one warp per query row ----------------
// writes output as bf16 hi/lo split ready for the o-proj GEMM
__global__ void attn_kernel(const float* __restrict__ Q, const float* __restrict__ K,
                            const float* __restrict__ V,
                            __nv_bfloat16* __restrict__ Oh, __nv_bfloat16* __restrict__ Ol) {
    __shared__ float qs[8][HD];
    __shared__ float sc[8][SEQ];
    int w = threadIdx.x >> 5, l = threadIdx.x & 31;
    int g = blockIdx.x * 8 + w;
    int s = g & (SEQ - 1);
    int bh = g >> 10;
    int h = bh % NH, b = bh / NH;
    int kvh = h / (NH / NKV);
    const float* qp = Q + (((size_t)(b * SEQ + s)) * NH + h) * HD;
    qs[w][l] = qp[l]; qs[w][l + 32] = qp[l + 32];
    __syncwarp();
    const float* Kb = K + ((size_t)b * SEQ * NKV + kvh) * HD;
    const float* Vb = V + ((size_t)b * SEQ * NKV + kvh) * HD;
    for (int j = l; j <= s; j += 32) {
        const float4* kp = (const float4*)(Kb + (size_t)j * (NKV * HD));
        float d = 0.f;
        #pragma unroll
        for (int i = 0; i < 16; i++) {
            float4 kk = kp[i];
            d += qs[w][4*i] * kk.x + qs[w][4*i+1] * kk.y + qs[w][4*i+2] * kk.z + qs[w][4*i+3] * kk.w;
        }
        sc[w][j] = d * 0.125f;
    }
    __syncwarp();
    float m = -1e30f;
    for (int j = l; j <= s; j += 32) m = fmaxf(m, sc[w][j]);
    #pragma unroll
    for (int o = 16; o; o >>= 1) m = fmaxf(m, __shfl_xor_sync(~0u, m, o));
    float sum = 0.f;
    for (int j = l; j <= s; j += 32) { float p = expf(sc[w][j] - m); sc[w][j] = p; sum += p; }
    #pragma unroll
    for (int o = 16; o; o >>= 1) sum += __shfl_xor_sync(~0u, sum, o);
    __syncwarp();
    float oa = 0.f, ob = 0.f;
    int j = 0;
    for (; j + 4 <= s + 1; j += 4) {
        #pragma unroll
        for (int u = 0; u < 4; u++) {
            float p = sc[w][j + u];
            const float* vp = Vb + (size_t)(j + u) * (NKV * HD);
            oa += p * vp[l]; ob += p * vp[l + 32];
        }
    }
    for (; j <= s; j++) {
        float p = sc[w][j];
        const float* vp = Vb + (size_t)j * (NKV * HD);
        oa += p * vp[l]; ob += p * vp[l + 32];
    }
    float invs = 1.0f / sum;
    size_t op = (((size_t)(b * SEQ + s)) * NH + h) * HD;
    split1(oa * invs, &Oh[op + l], &Ol[op + l]);
    split1(ob * invs, &Oh[op + l + 32], &Ol[op + l + 32]);
}

// ---------------- causal depthwise conv -> bf16 hi/lo split ----------------
__global__ void conv_split_kernel(const float* __restrict__ T, const float* __restrict__ W4,
                                  const float* __restrict__ cb,
                                  __nv_bfloat16* __restrict__ Yh, __nv_bfloat16* __restrict__ Yl) {
    int idx = blockIdx.x * blockDim.x + threadIdx.x;
    int c = idx % Hdim;
    int row = idx / Hdim;
    int s = row & (SEQ - 1);
    int b = row / SEQ;
    const float* w = W4 + (size_t)c * KCONV;
    float acc = cb[c];
    #pragma unroll
    for (int j = 0; j < KCONV; j++) {
        int sp = s - (KCONV - 1) + j;
        if (sp >= 0) {
            const float* tr = T + ((size_t)(b * SEQ + sp)) * H3;
            acc += w[j] * tr[c] * tr[2 * Hdim + c];
        }
    }
    float Cg = T[(size_t)row * H3 + Hdim + c];
    split1(Cg * acc, &Yh[(size_t)row * Hdim + c], &Yl[(size_t)row * Hdim + c]);
}

// ---------------- silu(gate)*up -> bf16 hi/lo split ----------------
__global__ void silu_mul_split_kernel(const float* __restrict__ G, const float* __restrict__ U,
                                      __nv_bfloat16* __restrict__ Hh, __nv_bfloat16* __restrict__ Hl) {
    int i = blockIdx.x * blockDim.x + threadIdx.x;
    float g = G[i];
    float y = (g / (1.0f + expf(-g))) * U[i];
    split1(y, &Hh[i], &Hl[i]);
}

// ---------------- host-side plumbing ----------------
static void gemm(const __nv_bfloat16* Ah, const __nv_bfloat16* Al,
                 const __nv_bfloat16* Bh, const __nv_bfloat16* Bl,
                 float* C, int M, int N, int K, const float* bias, const float* res) {
    dim3 grid(N / 128, M / 128);
    gemm_bf16x3<<<grid, 256, SMEM_TOTAL>>>(Ah, Al, Bh, Bl, C, M, N, K, bias, res);
}

static void wsplit(const float* src, __nv_bfloat16* H, __nv_bfloat16* L, size_t n) {
    wsplit_kernel<<<(unsigned)(n / 1024), 256>>>((const float4*)src, H, L);
}

extern "C" void kernel_launch(void* const* d_in, const int* in_sizes, int n_in,
                              void* d_out, int out_size) {
    const int*   tokens  = (const int*)  d_in[0];
    const float* embed   = (const float*)d_in[1];
    const float* qw      = (const float*)d_in[2];
    const float* kw      = (const float*)d_in[3];
    const float* vw      = (const float*)d_in[4];
    const float* ow      = (const float*)d_in[5];
    const float* qln     = (const float*)d_in[6];
    const float* kln     = (const float*)d_in[7];
    const float* a_gate  = (const float*)d_in[8];
    const float* a_up    = (const float*)d_in[9];
    const float* a_down  = (const float*)d_in[10];
    const float* a_ln1   = (const float*)d_in[11];
    const float* a_ln2   = (const float*)d_in[12];
    const float* conv_w  = (const float*)d_in[13];
    const float* conv_b  = (const float*)d_in[14];
    const float* in_w    = (const float*)d_in[15];
    const float* in_b    = (const float*)d_in[16];
    const float* out_w   = (const float*)d_in[17];
    const float* out_b   = (const float*)d_in[18];
    const float* c_gate  = (const float*)d_in[19];
    const float* c_up    = (const float*)d_in[20];
    const float* c_down  = (const float*)d_in[21];
    const float* c_ln1   = (const float*)d_in[22];
    const float* c_ln2   = (const float*)d_in[23];
    const float* finln   = (const float*)d_in[24];
    const float* lm_head = (const float*)d_in[25];

    cudaFuncSetAttribute(gemm_bf16x3, cudaFuncAttributeMaxDynamicSharedMemorySize, SMEM_TOTAL);

    float *x, *q, *k, *v, *t1, *t2;
    __nv_bfloat16 *ah, *al, *wh, *wl;
    cudaGetSymbolAddress((void**)&x,  g_x);
    cudaGetSymbolAddress((void**)&q,  g_q);
    cudaGetSymbolAddress((void**)&k,  g_k);
    cudaGetSymbolAddress((void**)&v,  g_v);
    cudaGetSymbolAddress((void**)&t1, g_t1);
    cudaGetSymbolAddress((void**)&t2, g_t2);
    cudaGetSymbolAddress((void**)&ah, g_ah);
    cudaGetSymbolAddress((void**)&al, g_al);
    cudaGetSymbolAddress((void**)&wh, g_wh);
    cudaGetSymbolAddress((void**)&wl, g_wl);

    // split all weights to bf16 hi/lo
    wsplit(qw,      wh + OFF_QW,   wl + OFF_QW,   2359296ull);
    wsplit(kw,      wh + OFF_KW,   wl + OFF_KW,   786432ull);
    wsplit(vw,      wh + OFF_VW,   wl + OFF_VW,   786432ull);
    wsplit(ow,      wh + OFF_OW,   wl + OFF_OW,   2359296ull);
    wsplit(a_gate,  wh + OFF_AG,   wl + OFF_AG,   9437184ull);
    wsplit(a_up,    wh + OFF_AU,   wl + OFF_AU,   9437184ull);
    wsplit(a_down,  wh + OFF_AD,   wl + OFF_AD,   9437184ull);
    wsplit(in_w,    wh + OFF_INW,  wl + OFF_INW,  14155776ull);
    wsplit(out_w,   wh + OFF_OUTW, wl + OFF_OUTW, 4718592ull);
    wsplit(c_gate,  wh + OFF_CG,   wl + OFF_CG,   18874368ull);
    wsplit(c_up,    wh + OFF_CU,   wl + OFF_CU,   18874368ull);
    wsplit(c_down,  wh + OFF_CD,   wl + OFF_CD,   18874368ull);
    wsplit(lm_head, wh + OFF_LM,   wl + OFF_LM,   38633472ull);

    embed_kernel<<<ROWS, 256>>>(tokens, embed, x);

    int ai = 0, ci = 0;
    for (int l = 0; l < 12; l++) {
        bool full = (l == 2 || l == 5 || l == 8 || l == 11);
        if (full) {
            size_t oq = OFF_QW + (size_t)ai * Hdim * Hdim;
            size_t ok = OFF_KW + (size_t)ai * NKV * HD * Hdim;
            size_t ov = OFF_VW + (size_t)ai * NKV * HD * Hdim;
            size_t oo = OFF_OW + (size_t)ai * Hdim * Hdim;
            size_t og = OFF_AG + (size_t)ai * IM * Hdim;
            size_t ou = OFF_AU + (size_t)ai * IM * Hdim;
            size_t od = OFF_AD + (size_t)ai * Hdim * IM;
            rmsnorm_split_kernel<<<ROWS, 256>>>(x, a_ln1 + (size_t)ai * Hdim, ah, al, Hdim);
            gemm(ah, al, wh + oq, wl + oq, q, ROWS, Hdim,     Hdim, 0, 0);
            gemm(ah, al, wh + ok, wl + ok, k, ROWS, NKV * HD, Hdim, 0, 0);
            gemm(ah, al, wh + ov, wl + ov, v, ROWS, NKV * HD, Hdim, 0, 0);
            qknorm_rope_kernel<<<ROWS * 16 / 8, 256>>>(q, k, qln + (size_t)ai * HD, kln + (size_t)ai * HD);
            attn_kernel<<<BATCH * NH * SEQ / 8, 256>>>(q, k, v, ah, al);
            gemm(ah, al, wh + oo, wl + oo, x, ROWS, Hdim, Hdim, 0, x);
            rmsnorm_split_kernel<<<ROWS, 256>>>(x, a_ln2 + (size_t)ai * Hdim, ah, al, Hdim);
            gemm(ah, al, wh + og, wl + og, t1, ROWS, IM, Hdim, 0, 0);
            gemm(ah, al, wh + ou, wl + ou, t2, ROWS, IM, Hdim, 0, 0);
            silu_mul_split_kernel<<<(ROWS * IM) / 256, 256>>>(t1, t2, ah, al);
            gemm(ah, al, wh + od, wl + od, x, ROWS, Hdim, IM, 0, x);
            ai++;
        } else {
            size_t oi = OFF_INW  + (size_t)ci * H3 * Hdim;
            size_t oo = OFF_OUTW + (size_t)ci * Hdim * Hdim;
            size_t og = OFF_CG   + (size_t)ci * IM * Hdim;
            size_t ou = OFF_CU   + (size_t)ci * IM * Hdim;
            size_t od = OFF_CD   + (size_t)ci * Hdim * IM;
            rmsnorm_split_kernel<<<ROWS, 256>>>(x, c_ln1 + (size_t)ci * Hdim, ah, al, Hdim);
            gemm(ah, al, wh + oi, wl + oi, t1, ROWS, H3, Hdim, in_b + (size_t)ci * H3, 0);
            conv_split_kernel<<<(ROWS * Hdim) / 256, 256>>>(t1, conv_w + (size_t)ci * Hdim * KCONV,
                                                            conv_b + (size_t)ci * Hdim, ah, al);
            gemm(ah, al, wh + oo, wl + oo, x, ROWS, Hdim, Hdim, out_b + (size_t)ci * Hdim, x);
            rmsnorm_split_kernel<<<ROWS, 256>>>(x, c_ln2 + (size_t)ci * Hdim, ah, al, Hdim);
            gemm(ah, al, wh + og, wl + og, t1, ROWS, IM, Hdim, 0, 0);
            gemm(ah, al, wh + ou, wl + ou, t2, ROWS, IM, Hdim, 0, 0);
            silu_mul_split_kernel<<<(ROWS * IM) / 256, 256>>>(t1, t2, ah, al);
            gemm(ah, al, wh + od, wl + od, x, ROWS, Hdim, IM, 0, x);
            ci++;
        }
    }
    rmsnorm_split_kernel<<<ROWS, 256>>>(x, finln, ah, al, Hdim);
    gemm(ah, al, wh + OFF_LM, wl + OFF_LM, (float*)d_out, ROWS, VOCAB, Hdim, 0, 0);
}